// round 4
// baseline (speedup 1.0000x reference)
#include <cuda_runtime.h>
#include <cstdint>

typedef unsigned long long u64;

#define TT 512
#define BB 64
#define DD 512
#define HH 512
#define G4 2048
#define NCTA 128

// ---------------------------------------------------------------------------
// Device-global scratch
// ---------------------------------------------------------------------------
__device__ float g_G[(size_t)2 * TT * G4 * BB];   // 512 MB precomputed x@Wih^T + bias
__device__ float g_h[2][2][HH][BB];               // [buf][dir][k][b]
__device__ unsigned g_bar_count;
__device__ volatile unsigned g_bar_gen;

// ---------------------------------------------------------------------------
// f32x2 packed helpers (sm_103a FFMA2: double-rate fp32)
// ---------------------------------------------------------------------------
__device__ __forceinline__ u64 pk2(float a, float b) {
    u64 r; asm("mov.b64 %0, {%1,%2};" : "=l"(r) : "f"(a), "f"(b)); return r;
}
__device__ __forceinline__ void fma2(u64& d, u64 a, u64 b) {
    asm("fma.rn.f32x2 %0, %1, %2, %0;" : "+l"(d) : "l"(a), "l"(b));
}
__device__ __forceinline__ float2 unpk(u64 v) {
    float2 r; asm("mov.b64 {%0,%1}, %2;" : "=f"(r.x), "=f"(r.y) : "l"(v)); return r;
}
__device__ __forceinline__ float sigf(float x)  { return 1.0f / (1.0f + __expf(-x)); }
__device__ __forceinline__ float tanhfast(float x) {
    return 2.0f / (1.0f + __expf(-2.0f * x)) - 1.0f;
}

__device__ __forceinline__ unsigned smem_u32(const void* p) {
    return (unsigned)__cvta_generic_to_shared(p);
}
__device__ __forceinline__ void cp16(unsigned dst, const void* src) {
    asm volatile("cp.async.cg.shared.global [%0], [%1], 16;" :: "r"(dst), "l"(src) : "memory");
}
__device__ __forceinline__ void cp_commit() {
    asm volatile("cp.async.commit_group;" ::: "memory");
}
__device__ __forceinline__ void cp_wait(int n) {
    switch (n) {
        case 0: asm volatile("cp.async.wait_group 0;" ::: "memory"); break;
        case 1: asm volatile("cp.async.wait_group 1;" ::: "memory"); break;
        case 2: asm volatile("cp.async.wait_group 2;" ::: "memory"); break;
        case 3: asm volatile("cp.async.wait_group 3;" ::: "memory"); break;
        case 4: asm volatile("cp.async.wait_group 4;" ::: "memory"); break;
        case 5: asm volatile("cp.async.wait_group 5;" ::: "memory"); break;
        case 6: asm volatile("cp.async.wait_group 6;" ::: "memory"); break;
        case 7: asm volatile("cp.async.wait_group 7;" ::: "memory"); break;
        default: asm volatile("cp.async.wait_group 8;" ::: "memory"); break;
    }
}

// ---------------------------------------------------------------------------
// Grid barrier: all NCTA CTAs resident (1 CTA/SM, 128 <= 148 SMs)
// ---------------------------------------------------------------------------
__device__ __forceinline__ void grid_barrier() {
    __syncthreads();
    if (threadIdx.x == 0) {
        unsigned gen = g_bar_gen;
        __threadfence();
        if (atomicAdd(&g_bar_count, 1u) == NCTA - 1) {
            g_bar_count = 0;
            __threadfence();
            g_bar_gen = gen + 1;
        } else {
            while (g_bar_gen == gen) { __nanosleep(64); }
        }
        __threadfence();
    }
    __syncthreads();
}

// ---------------------------------------------------------------------------
// Phase 1 (unchanged from R2, known-good):
// G[dir][s][n][b] = bias[n] + sum_d W[n][d] * x[t][b][d]
// ---------------------------------------------------------------------------
__global__ void __launch_bounds__(256) phase1_kernel(
    const float* __restrict__ x,
    const float* __restrict__ Wf, const float* __restrict__ Wr,
    const float* __restrict__ bif, const float* __restrict__ bhf,
    const float* __restrict__ bir, const float* __restrict__ bhr)
{
    __shared__ __align__(16) float Wt[32][132];
    __shared__ __align__(16) float Xt[32][68];

    const int tid = threadIdx.x;
    const int n0  = blockIdx.x * 128;
    const int s   = blockIdx.y;
    const int dir = blockIdx.z;
    const int tt  = dir ? (TT - 1 - s) : s;
    const float* __restrict__ W = dir ? Wr : Wf;

    const int bg = tid & 15;
    const int ng = tid >> 4;

    u64 acc[8][2];
#pragma unroll
    for (int i = 0; i < 8; i++) { acc[i][0] = 0ull; acc[i][1] = 0ull; }

    const float* xbase = x + (size_t)tt * BB * DD;

    for (int d0 = 0; d0 < DD; d0 += 32) {
        __syncthreads();
#pragma unroll
        for (int i = 0; i < 4; i++) {
            int lin = tid + 256 * i;
            int n = lin >> 3, kq = lin & 7;
            float4 w = *(const float4*)(W + (size_t)(n0 + n) * DD + d0 + kq * 4);
            Wt[kq*4+0][n] = w.x; Wt[kq*4+1][n] = w.y;
            Wt[kq*4+2][n] = w.z; Wt[kq*4+3][n] = w.w;
        }
#pragma unroll
        for (int i = 0; i < 2; i++) {
            int lin = tid + 256 * i;
            int b = lin >> 3, kq = lin & 7;
            float4 v = *(const float4*)(xbase + (size_t)b * DD + d0 + kq * 4);
            Xt[kq*4+0][b] = v.x; Xt[kq*4+1][b] = v.y;
            Xt[kq*4+2][b] = v.z; Xt[kq*4+3][b] = v.w;
        }
        __syncthreads();
#pragma unroll 8
        for (int k = 0; k < 32; k++) {
            float4 xa = *(const float4*)&Xt[k][bg * 4];
            u64 xv0 = pk2(xa.x, xa.y);
            u64 xv1 = pk2(xa.z, xa.w);
            float wv[8];
            *(float4*)&wv[0] = *(const float4*)&Wt[k][ng * 8];
            *(float4*)&wv[4] = *(const float4*)&Wt[k][ng * 8 + 4];
#pragma unroll
            for (int i = 0; i < 8; i++) {
                u64 w = pk2(wv[i], wv[i]);
                fma2(acc[i][0], w, xv0);
                fma2(acc[i][1], w, xv1);
            }
        }
    }

    const float* bi = dir ? bir : bif;
    const float* bh = dir ? bhr : bhf;
    float* Gp = g_G + ((size_t)(dir * TT + s) * G4 + n0 + ng * 8) * BB;
#pragma unroll
    for (int i = 0; i < 8; i++) {
        int n = n0 + ng * 8 + i;
        float bsum = bi[n] + bh[n];
        float2 p0 = unpk(acc[i][0]);
        float2 p1 = unpk(acc[i][1]);
        float4 o = make_float4(p0.x + bsum, p0.y + bsum, p1.x + bsum, p1.y + bsum);
        *(float4*)(Gp + (size_t)i * BB + bg * 4) = o;
    }
}

// ---------------------------------------------------------------------------
// Phase 2 v2: persistent recurrence. 128 CTAs x 256 threads.
// CTA (dir, j0): 8 hidden units = 32 gate rows. Whh rows resident in SMEM
// row-major Ws[r][k]. Full h vector (128 KB) staged in SMEM per step via
// 8 cp.async groups issued up-front, staged wait_group. G tile for the next
// step prefetched across the grid barrier (hides DRAM latency).
// Thread (r = tid>>3, bo = tid&7): row r, batch lanes 8*bo..8*bo+7.
// ---------------------------------------------------------------------------
__global__ void __launch_bounds__(256) phase2_kernel(
    const float* __restrict__ Whf, const float* __restrict__ Whr,
    const float* __restrict__ mask, float* __restrict__ out)
{
    extern __shared__ __align__(16) float sm[];
    float* Ws   = sm;                   // [32][512]   64 KB
    float* hall = Ws + 32 * 512;        // [512][64]  128 KB
    float* Gs   = hall + 512 * 64;      // [2][32][64] 16 KB
    float* gbuf = Gs + 2 * 32 * 64;     // [32][64]     8 KB
    float* csm  = gbuf + 32 * 64;       // [8][64]      2 KB  (u,b)
    float* hosm = csm + 8 * 64;         // [64][8]      2 KB  (b,u)

    const int tid = threadIdx.x;
    const int cid = blockIdx.x;
    const int dir = cid >> 6;
    const int j0  = (cid & 63) * 8;
    const float* __restrict__ Whh = dir ? Whr : Whf;

    // Load Whh rows (row-major per gate-row) into Ws[r][k]
    for (int i = tid; i < 32 * 128; i += 256) {
        int rr = i >> 7, kq = i & 127;
        int gate = rr >> 3, u = rr & 7;
        float4 w = *(const float4*)(Whh + (size_t)(gate * HH + j0 + u) * HH + kq * 4);
        *(float4*)&Ws[rr * 512 + kq * 4] = w;
    }
    // Zero state (determinism across graph replays)
    for (int i = tid; i < 8 * 64; i += 256) {
        csm[i] = 0.0f;
        hosm[i] = 0.0f;
        g_h[0][dir][j0 + (i >> 6)][i & 63] = 0.0f;
    }

    // Prefetch G tile for step 0 (group committed before the first barrier)
    {
        const float* base = g_G + (size_t)(dir * TT + 0) * G4 * BB;
#pragma unroll
        for (int i = 0; i < 2; i++) {
            int q = tid + 256 * i;
            int gate = q >> 7, off = q & 127;
            const float* src = base + ((size_t)(gate * HH + j0)) * BB + off * 4;
            cp16(smem_u32(Gs + gate * 8 * 64 + off * 4), src);
        }
        cp_commit();
    }
    grid_barrier();

    const int r  = tid >> 3;       // 0..31  (gate row)
    const int bo = tid & 7;        // batch group
    const float* wrow = Ws + r * 512;
    const float* hbo  = hall + bo * 8;

    for (int s = 0; s < TT; s++) {
        const int pb = s & 1, nb = pb ^ 1;
        const int tg = dir ? (TT - 1 - s) : s;
        const float m = __ldg(mask + (size_t)tg * BB + (tid & 63));

        // Issue all 8 h-chunk groups up front (16 KB each)
        {
            const char* src0 = (const char*)&g_h[pb][dir][0][0];
            unsigned dst0 = smem_u32(hall);
#pragma unroll
            for (int ch = 0; ch < 8; ch++) {
#pragma unroll
                for (int i = 0; i < 4; i++)
                    cp16(dst0 + ch * 16384 + tid * 16 + i * 4096,
                         src0 + ch * 16384 + tid * 16 + i * 4096);
                cp_commit();
            }
        }

        // Wait for G tile (committed last step), then init accumulators
        cp_wait(8);
        __syncthreads();
        u64 acc[4];
        {
            const float* Gp = Gs + (s & 1) * 2048 + r * 64 + bo * 8;
            ulonglong2 q0 = *(const ulonglong2*)Gp;
            ulonglong2 q1 = *(const ulonglong2*)(Gp + 4);
            acc[0] = q0.x; acc[1] = q0.y; acc[2] = q1.x; acc[3] = q1.y;
        }

        // k-loop: 8 chunks of 64, staged waits
#pragma unroll
        for (int c = 0; c < 8; c++) {
            cp_wait(7 - c);
            __syncthreads();
#pragma unroll 4
            for (int k4 = 0; k4 < 16; k4++) {
                const int kk = c * 64 + k4 * 4;
                float4 w4 = *(const float4*)(wrow + kk);
                const float* hp = hbo + kk * 64;
                u64 w; ulonglong2 p, q;
                w = pk2(w4.x, w4.x);
                p = *(const ulonglong2*)(hp);
                q = *(const ulonglong2*)(hp + 4);
                fma2(acc[0], w, p.x); fma2(acc[1], w, p.y);
                fma2(acc[2], w, q.x); fma2(acc[3], w, q.y);
                w = pk2(w4.y, w4.y);
                p = *(const ulonglong2*)(hp + 64);
                q = *(const ulonglong2*)(hp + 68);
                fma2(acc[0], w, p.x); fma2(acc[1], w, p.y);
                fma2(acc[2], w, q.x); fma2(acc[3], w, q.y);
                w = pk2(w4.z, w4.z);
                p = *(const ulonglong2*)(hp + 128);
                q = *(const ulonglong2*)(hp + 132);
                fma2(acc[0], w, p.x); fma2(acc[1], w, p.y);
                fma2(acc[2], w, q.x); fma2(acc[3], w, q.y);
                w = pk2(w4.w, w4.w);
                p = *(const ulonglong2*)(hp + 192);
                q = *(const ulonglong2*)(hp + 196);
                fma2(acc[0], w, p.x); fma2(acc[1], w, p.y);
                fma2(acc[2], w, q.x); fma2(acc[3], w, q.y);
            }
        }

        // Gate pre-activations -> gbuf
        {
            float* gb = gbuf + r * 64 + bo * 8;
            float2 t0 = unpk(acc[0]), t1 = unpk(acc[1]);
            *(float4*)gb = make_float4(t0.x, t0.y, t1.x, t1.y);
            t0 = unpk(acc[2]); t1 = unpk(acc[3]);
            *(float4*)(gb + 4) = make_float4(t0.x, t0.y, t1.x, t1.y);
        }
        __syncthreads();

        // Gates, state update, mask blend, h publish
        {
            const int b = tid & 63;
#pragma unroll
            for (int it = 0; it < 2; it++) {
                const int u = (tid >> 6) + it * 4;
                float ig = sigf(gbuf[(u     ) * 64 + b]);
                float fg = sigf(gbuf[( 8 + u) * 64 + b]);
                float gg = tanhfast(gbuf[(16 + u) * 64 + b]);
                float og = sigf(gbuf[(24 + u) * 64 + b]);
                float c_old = csm[u * 64 + b];
                float c2 = fg * c_old + ig * gg;
                float h2 = og * tanhfast(c2);
                float c_new = c_old + m * (c2 - c_old);
                float h_old = hosm[b * 8 + u];
                float h_new = h_old + m * (h2 - h_old);
                csm[u * 64 + b]  = c_new;
                hosm[b * 8 + u] = h_new;
                g_h[nb][dir][j0 + u][b] = h_new;
            }
        }
        __syncthreads();

        // Coalesced output: 128 threads x STG.128
        if (tid < 128) {
            const int b = tid >> 1, half = tid & 1;
            *(float4*)&out[(size_t)tg * (BB * 1024) + (size_t)b * 1024
                           + dir * HH + j0 + half * 4]
                = *(const float4*)&hosm[b * 8 + half * 4];
        }

        if (s + 1 < TT) {
            // Prefetch next step's G tile across the barrier
            const float* base = g_G + (size_t)(dir * TT + (s + 1)) * G4 * BB;
            float* GsN = Gs + ((s + 1) & 1) * 2048;
#pragma unroll
            for (int i = 0; i < 2; i++) {
                int q = tid + 256 * i;
                int gate = q >> 7, off = q & 127;
                const float* src = base + ((size_t)(gate * HH + j0)) * BB + off * 4;
                cp16(smem_u32(GsN + gate * 8 * 64 + off * 4), src);
            }
            cp_commit();
            grid_barrier();
        }
    }
}

// ---------------------------------------------------------------------------
// Launch
// ---------------------------------------------------------------------------
extern "C" void kernel_launch(void* const* d_in, const int* in_sizes, int n_in,
                              void* d_out, int out_size) {
    const float* x_data = (const float*)d_in[0];
    const float* x_mask = (const float*)d_in[1];
    const float* Wih_f  = (const float*)d_in[2];
    const float* Whh_f  = (const float*)d_in[3];
    const float* bih_f  = (const float*)d_in[4];
    const float* bhh_f  = (const float*)d_in[5];
    const float* Wih_r  = (const float*)d_in[6];
    const float* Whh_r  = (const float*)d_in[7];
    const float* bih_r  = (const float*)d_in[8];
    const float* bhh_r  = (const float*)d_in[9];
    float* out = (float*)d_out;

    static bool attr_set = false;
    if (!attr_set) {
        cudaFuncSetAttribute(phase2_kernel,
                             cudaFuncAttributeMaxDynamicSharedMemorySize, 225280);
        attr_set = true;
    }

    dim3 g1(16, 512, 2);
    phase1_kernel<<<g1, 256>>>(x_data, Wih_f, Wih_r, bih_f, bhh_f, bih_r, bhh_r);
    phase2_kernel<<<NCTA, 256, 225280>>>(Whh_f, Whh_r, x_mask, out);
}

// round 5
// speedup vs baseline: 2.1266x; 2.1266x over previous
#include <cuda_runtime.h>
#include <cstdint>

typedef unsigned long long u64;

#define TT 512
#define BB 64
#define DD 512
#define HH 512
#define G4 2048
#define NCTA 128

// ---------------------------------------------------------------------------
// Device-global scratch
// ---------------------------------------------------------------------------
__device__ float g_G[(size_t)2 * TT * G4 * BB];   // 512 MB precomputed x@Wih^T + bias
__device__ float g_h[2][2][HH][BB];               // [buf][dir][k][b]
__device__ unsigned g_bar_count;
__device__ volatile unsigned g_bar_gen;

// ---------------------------------------------------------------------------
// f32x2 packed helpers (sm_103a FFMA2: double-rate fp32)
// ---------------------------------------------------------------------------
__device__ __forceinline__ u64 pk2(float a, float b) {
    u64 r; asm("mov.b64 %0, {%1,%2};" : "=l"(r) : "f"(a), "f"(b)); return r;
}
__device__ __forceinline__ void fma2(u64& d, u64 a, u64 b) {
    asm("fma.rn.f32x2 %0, %1, %2, %0;" : "+l"(d) : "l"(a), "l"(b));
}
__device__ __forceinline__ float2 unpk(u64 v) {
    float2 r; asm("mov.b64 {%0,%1}, %2;" : "=f"(r.x), "=f"(r.y) : "l"(v)); return r;
}
__device__ __forceinline__ float sigf(float x)  { return 1.0f / (1.0f + __expf(-x)); }
__device__ __forceinline__ float tanhfast(float x) {
    return 2.0f / (1.0f + __expf(-2.0f * x)) - 1.0f;
}

__device__ __forceinline__ unsigned smem_u32(const void* p) {
    return (unsigned)__cvta_generic_to_shared(p);
}
__device__ __forceinline__ void cp16(unsigned dst, const void* src) {
    asm volatile("cp.async.cg.shared.global [%0], [%1], 16;" :: "r"(dst), "l"(src) : "memory");
}
__device__ __forceinline__ void cp_commit() {
    asm volatile("cp.async.commit_group;" ::: "memory");
}
__device__ __forceinline__ void cp_wait0() {
    asm volatile("cp.async.wait_group 0;" ::: "memory");
}

// mbarrier helpers ------------------------------------------------------------
__device__ __forceinline__ void mbar_init(unsigned addr, unsigned cnt) {
    asm volatile("mbarrier.init.shared.b64 [%0], %1;" :: "r"(addr), "r"(cnt) : "memory");
}
__device__ __forceinline__ void mbar_expect_tx(unsigned addr, unsigned bytes) {
    asm volatile("mbarrier.arrive.expect_tx.shared.b64 _, [%0], %1;"
                 :: "r"(addr), "r"(bytes) : "memory");
}
__device__ __forceinline__ void bulk_g2s(unsigned dst, const void* src,
                                         unsigned bytes, unsigned mbar) {
    asm volatile("cp.async.bulk.shared::cta.global.mbarrier::complete_tx::bytes "
                 "[%0], [%1], %2, [%3];"
                 :: "r"(dst), "l"(src), "r"(bytes), "r"(mbar) : "memory");
}
__device__ __forceinline__ void mbar_wait(unsigned addr, unsigned parity) {
    unsigned done;
    asm volatile(
        "{\n\t.reg .pred p;\n\t"
        "mbarrier.try_wait.parity.acquire.cta.shared::cta.b64 p, [%1], %2;\n\t"
        "selp.b32 %0, 1, 0, p;\n\t}"
        : "=r"(done) : "r"(addr), "r"(parity) : "memory");
    if (!done) {
        asm volatile(
            "{\n\t.reg .pred P1;\n\t"
            "WL_%=:\n\t"
            "mbarrier.try_wait.parity.acquire.cta.shared::cta.b64 P1, [%0], %1, 0x989680;\n\t"
            "@P1 bra.uni WD_%=;\n\t"
            "bra.uni WL_%=;\n\t"
            "WD_%=:\n\t}"
            :: "r"(addr), "r"(parity) : "memory");
    }
}

// ---------------------------------------------------------------------------
// Grid barrier: all NCTA CTAs resident (1 CTA/SM, 128 <= 148 SMs)
// ---------------------------------------------------------------------------
__device__ __forceinline__ void grid_barrier() {
    __syncthreads();
    if (threadIdx.x == 0) {
        unsigned gen = g_bar_gen;
        __threadfence();
        if (atomicAdd(&g_bar_count, 1u) == NCTA - 1) {
            g_bar_count = 0;
            __threadfence();
            g_bar_gen = gen + 1;
        } else {
            while (g_bar_gen == gen) { __nanosleep(32); }
        }
        __threadfence();
    }
    __syncthreads();
}

// ---------------------------------------------------------------------------
// Phase 1 (unchanged, known-good):
// G[dir][s][n][b] = bias[n] + sum_d W[n][d] * x[t][b][d]
// ---------------------------------------------------------------------------
__global__ void __launch_bounds__(256) phase1_kernel(
    const float* __restrict__ x,
    const float* __restrict__ Wf, const float* __restrict__ Wr,
    const float* __restrict__ bif, const float* __restrict__ bhf,
    const float* __restrict__ bir, const float* __restrict__ bhr)
{
    __shared__ __align__(16) float Wt[32][132];
    __shared__ __align__(16) float Xt[32][68];

    const int tid = threadIdx.x;
    const int n0  = blockIdx.x * 128;
    const int s   = blockIdx.y;
    const int dir = blockIdx.z;
    const int tt  = dir ? (TT - 1 - s) : s;
    const float* __restrict__ W = dir ? Wr : Wf;

    const int bg = tid & 15;
    const int ng = tid >> 4;

    u64 acc[8][2];
#pragma unroll
    for (int i = 0; i < 8; i++) { acc[i][0] = 0ull; acc[i][1] = 0ull; }

    const float* xbase = x + (size_t)tt * BB * DD;

    for (int d0 = 0; d0 < DD; d0 += 32) {
        __syncthreads();
#pragma unroll
        for (int i = 0; i < 4; i++) {
            int lin = tid + 256 * i;
            int n = lin >> 3, kq = lin & 7;
            float4 w = *(const float4*)(W + (size_t)(n0 + n) * DD + d0 + kq * 4);
            Wt[kq*4+0][n] = w.x; Wt[kq*4+1][n] = w.y;
            Wt[kq*4+2][n] = w.z; Wt[kq*4+3][n] = w.w;
        }
#pragma unroll
        for (int i = 0; i < 2; i++) {
            int lin = tid + 256 * i;
            int b = lin >> 3, kq = lin & 7;
            float4 v = *(const float4*)(xbase + (size_t)b * DD + d0 + kq * 4);
            Xt[kq*4+0][b] = v.x; Xt[kq*4+1][b] = v.y;
            Xt[kq*4+2][b] = v.z; Xt[kq*4+3][b] = v.w;
        }
        __syncthreads();
#pragma unroll 8
        for (int k = 0; k < 32; k++) {
            float4 xa = *(const float4*)&Xt[k][bg * 4];
            u64 xv0 = pk2(xa.x, xa.y);
            u64 xv1 = pk2(xa.z, xa.w);
            float wv[8];
            *(float4*)&wv[0] = *(const float4*)&Wt[k][ng * 8];
            *(float4*)&wv[4] = *(const float4*)&Wt[k][ng * 8 + 4];
#pragma unroll
            for (int i = 0; i < 8; i++) {
                u64 w = pk2(wv[i], wv[i]);
                fma2(acc[i][0], w, xv0);
                fma2(acc[i][1], w, xv1);
            }
        }
    }

    const float* bi = dir ? bir : bif;
    const float* bh = dir ? bhr : bhf;
    float* Gp = g_G + ((size_t)(dir * TT + s) * G4 + n0 + ng * 8) * BB;
#pragma unroll
    for (int i = 0; i < 8; i++) {
        int n = n0 + ng * 8 + i;
        float bsum = bi[n] + bh[n];
        float2 p0 = unpk(acc[i][0]);
        float2 p1 = unpk(acc[i][1]);
        float4 o = make_float4(p0.x + bsum, p0.y + bsum, p1.x + bsum, p1.y + bsum);
        *(float4*)(Gp + (size_t)i * BB + bg * 4) = o;
    }
}

// ---------------------------------------------------------------------------
// Phase 2 v3: persistent recurrence, full-width smem accesses.
// 128 CTAs x 256 threads. CTA (dir, j0): 8 hidden units = 32 gate rows.
// Warp (rg,bh,kh): rows 16rg..16rg+15 (8 f32x2 row-pair accs), b = 32bh+lane,
// k-half 256kh..+255. w loads: LDS.128 broadcast of row-pair u64s (no dup).
// h loads: LDS.32 lane-distinct (full 128B wavefront), dup'd once per k.
// h staged into smem by 4 x 32KB cp.async.bulk + mbarrier per step.
// SMEM floats: Ws[2][512][16]=16384 | hall[512][64]=32768 | Gs[32][64]=2048 |
//              gbuf2[2][32][64]=4096 | csm 512 | hosm 512 | 4 mbar (32B)
// ---------------------------------------------------------------------------
#define SM_WS    0
#define SM_HALL  16384
#define SM_GS    49152
#define SM_GBUF  51200
#define SM_CSM   55296
#define SM_HOSM  55808
#define SM_MBAR  56320          /* float index; byte 225280 */
#define SM_FLOATS 56336

__global__ void __launch_bounds__(256) phase2_kernel(
    const float* __restrict__ Whf, const float* __restrict__ Whr,
    const float* __restrict__ mask, float* __restrict__ out)
{
    extern __shared__ __align__(16) float sm[];
    float* Ws    = sm + SM_WS;
    float* hall  = sm + SM_HALL;
    float* Gs    = sm + SM_GS;
    float* gbuf2 = sm + SM_GBUF;
    float* csm   = sm + SM_CSM;
    float* hosm  = sm + SM_HOSM;
    const unsigned mbar0 = smem_u32(sm + SM_MBAR);
    const unsigned gs_sa = smem_u32(Gs);
    const unsigned hall_sa = smem_u32(hall);

    const int tid = threadIdx.x;
    const int cid = blockIdx.x;
    const int dir = cid >> 6;
    const int j0  = (cid & 63) * 8;
    const float* __restrict__ Whh = dir ? Whr : Whf;

    // --- init: Ws[rg][k][16] = Whh rows 16rg+rloc at col k -------------------
    for (int i = tid; i < 32 * 512; i += 256) {
        int rr = i >> 9, k = i & 511;          // rr: gate*8+u ordering
        int rg = rr >> 4, rloc = rr & 15;
        int gate = rr >> 3, u = rr & 7;
        Ws[((size_t)rg * 512 + k) * 16 + rloc] =
            Whh[(size_t)(gate * HH + j0 + u) * HH + k];
    }
    for (int i = tid; i < 8 * 64; i += 256) {
        csm[i] = 0.0f;
        hosm[i] = 0.0f;
        g_h[0][dir][j0 + (i >> 6)][i & 63] = 0.0f;
    }
    if (tid < 4) mbar_init(mbar0 + tid * 8, 1);
    __syncthreads();
    asm volatile("fence.proxy.async.shared::cta;" ::: "memory");

    // G prefetch for step 0
    {
        const float* base = g_G + (size_t)(dir * TT) * G4 * BB;
#pragma unroll
        for (int i = 0; i < 2; i++) {
            int q = tid + 256 * i;
            int gate = q >> 7, off = q & 127;
            const float* src = base + ((size_t)(gate * HH + j0)) * BB + off * 4;
            cp16(gs_sa + (unsigned)(gate * 512 + off * 4) * 4, src);
        }
        cp_commit();
    }
    grid_barrier();
    cp_wait0();
    __syncthreads();

    const int w    = tid >> 5;
    const int lane = tid & 31;
    const int rg   = w & 1;
    const int bh   = (w >> 1) & 1;
    const int kh   = w >> 2;                  // 0 or 1
    const int b    = bh * 32 + lane;
    const float* wbase = Ws + ((size_t)rg * 512 + kh * 256) * 16;
    const float* hbase = hall + (kh * 256) * 64 + b;

    for (int s = 0; s < TT; s++) {
        const int pb = s & 1, nb = pb ^ 1;
        const int tg = dir ? (TT - 1 - s) : s;

        // issue 4 bulk copies of h[pb] (32 KB each)
        if (tid < 4) {
            unsigned mb = mbar0 + tid * 8;
            mbar_expect_tx(mb, 32768u);
            bulk_g2s(hall_sa + (unsigned)tid * 32768u,
                     &g_h[pb][dir][tid * 128][0], 32768u, mb);
        }

        // accumulators: kh=0 carries G (input preact + bias), kh=1 zero
        u64 acc[8];
        if (kh == 0) {
            const float* Gp = Gs + (rg * 16) * 64 + b;
#pragma unroll
            for (int rp = 0; rp < 8; rp++)
                acc[rp] = pk2(Gp[(2 * rp) * 64], Gp[(2 * rp + 1) * 64]);
        } else {
#pragma unroll
            for (int rp = 0; rp < 8; rp++) acc[rp] = 0ull;
        }

        // k-loop over this warp's two 128-k chunks
#pragma unroll
        for (int half = 0; half < 2; half++) {
            mbar_wait(mbar0 + (kh * 2 + half) * 8, (unsigned)(s & 1));
            const float* wp = wbase + (size_t)half * 128 * 16;
            const float* hp = hbase + (size_t)half * 128 * 64;
#pragma unroll 4
            for (int k = 0; k < 128; k++) {
                float hv = hp[(size_t)k * 64];
                u64 hd = pk2(hv, hv);
                const float* wk = wp + (size_t)k * 16;
                ulonglong2 w01 = *(const ulonglong2*)(wk);
                ulonglong2 w23 = *(const ulonglong2*)(wk + 4);
                ulonglong2 w45 = *(const ulonglong2*)(wk + 8);
                ulonglong2 w67 = *(const ulonglong2*)(wk + 12);
                fma2(acc[0], w01.x, hd); fma2(acc[1], w01.y, hd);
                fma2(acc[2], w23.x, hd); fma2(acc[3], w23.y, hd);
                fma2(acc[4], w45.x, hd); fma2(acc[5], w45.y, hd);
                fma2(acc[6], w67.x, hd); fma2(acc[7], w67.y, hd);
            }
        }

        // write partials
        {
            float* gb = gbuf2 + kh * 2048 + (rg * 16) * 64 + b;
#pragma unroll
            for (int rp = 0; rp < 8; rp++) {
                float2 v = unpk(acc[rp]);
                gb[(2 * rp) * 64]     = v.x;
                gb[(2 * rp + 1) * 64] = v.y;
            }
        }
        __syncthreads();

        // gates, state update, mask blend, h publish
        {
            const int eb = tid & 63;
            const float m = __ldg(mask + (size_t)tg * BB + eb);
#pragma unroll
            for (int it = 0; it < 2; it++) {
                const int u = (tid >> 6) + it * 4;
                float pi = gbuf2[(u)      * 64 + eb] + gbuf2[2048 + (u)      * 64 + eb];
                float pf = gbuf2[(8 + u)  * 64 + eb] + gbuf2[2048 + (8 + u)  * 64 + eb];
                float pg = gbuf2[(16 + u) * 64 + eb] + gbuf2[2048 + (16 + u) * 64 + eb];
                float po = gbuf2[(24 + u) * 64 + eb] + gbuf2[2048 + (24 + u) * 64 + eb];
                float ig = sigf(pi);
                float fg = sigf(pf);
                float gg = tanhfast(pg);
                float og = sigf(po);
                float c_old = csm[u * 64 + eb];
                float c2 = fg * c_old + ig * gg;
                float h2 = og * tanhfast(c2);
                float c_new = c_old + m * (c2 - c_old);
                float h_old = hosm[eb * 8 + u];
                float h_new = h_old + m * (h2 - h_old);
                csm[u * 64 + eb] = c_new;
                hosm[eb * 8 + u] = h_new;
                g_h[nb][dir][j0 + u][eb] = h_new;
            }
        }
        __syncthreads();

        // coalesced output store
        if (tid < 128) {
            const int ob = tid >> 1, half = tid & 1;
            *(float4*)&out[(size_t)tg * (BB * 1024) + (size_t)ob * 1024
                           + dir * HH + j0 + half * 4]
                = *(const float4*)&hosm[ob * 8 + half * 4];
        }

        if (s + 1 < TT) {
            // G prefetch for s+1 (hides under barrier)
            const float* base = g_G + (size_t)(dir * TT + (s + 1)) * G4 * BB;
#pragma unroll
            for (int i = 0; i < 2; i++) {
                int q = tid + 256 * i;
                int gate = q >> 7, off = q & 127;
                const float* src = base + ((size_t)(gate * HH + j0)) * BB + off * 4;
                cp16(gs_sa + (unsigned)(gate * 512 + off * 4) * 4, src);
            }
            cp_commit();
            grid_barrier();
            cp_wait0();
            __syncthreads();
        }
    }
}

// ---------------------------------------------------------------------------
// Launch
// ---------------------------------------------------------------------------
extern "C" void kernel_launch(void* const* d_in, const int* in_sizes, int n_in,
                              void* d_out, int out_size) {
    const float* x_data = (const float*)d_in[0];
    const float* x_mask = (const float*)d_in[1];
    const float* Wih_f  = (const float*)d_in[2];
    const float* Whh_f  = (const float*)d_in[3];
    const float* bih_f  = (const float*)d_in[4];
    const float* bhh_f  = (const float*)d_in[5];
    const float* Wih_r  = (const float*)d_in[6];
    const float* Whh_r  = (const float*)d_in[7];
    const float* bih_r  = (const float*)d_in[8];
    const float* bhh_r  = (const float*)d_in[9];
    float* out = (float*)d_out;

    static bool attr_set = false;
    if (!attr_set) {
        cudaFuncSetAttribute(phase2_kernel,
                             cudaFuncAttributeMaxDynamicSharedMemorySize,
                             SM_FLOATS * 4);
        attr_set = true;
    }

    dim3 g1(16, 512, 2);
    phase1_kernel<<<g1, 256>>>(x_data, Wih_f, Wih_r, bih_f, bhh_f, bih_r, bhh_r);
    phase2_kernel<<<NCTA, 256, SM_FLOATS * 4>>>(Whh_f, Whh_r, x_mask, out);
}

// round 6
// speedup vs baseline: 2.2109x; 1.0396x over previous
#include <cuda_runtime.h>
#include <cstdint>

typedef unsigned long long u64;

#define TT 512
#define BB 64
#define DD 512
#define HH 512
#define G4 2048
#define NCTA 128

// ---------------------------------------------------------------------------
// Device-global scratch
// ---------------------------------------------------------------------------
__device__ float g_G[(size_t)2 * TT * G4 * BB];   // 512 MB precomputed x@Wih^T + bias
__device__ float g_h[2][2][HH][BB];               // [buf][dir][k][b]
__device__ unsigned g_bar_count;
__device__ volatile unsigned g_bar_gen;

// ---------------------------------------------------------------------------
// f32x2 packed helpers (sm_103a FFMA2)
// ---------------------------------------------------------------------------
__device__ __forceinline__ u64 pk2(float a, float b) {
    u64 r; asm("mov.b64 %0, {%1,%2};" : "=l"(r) : "f"(a), "f"(b)); return r;
}
__device__ __forceinline__ void fma2(u64& d, u64 a, u64 b) {
    asm("fma.rn.f32x2 %0, %1, %2, %0;" : "+l"(d) : "l"(a), "l"(b));
}
__device__ __forceinline__ float2 unpk(u64 v) {
    float2 r; asm("mov.b64 {%0,%1}, %2;" : "=f"(r.x), "=f"(r.y) : "l"(v)); return r;
}
__device__ __forceinline__ float sigf(float x)  { return 1.0f / (1.0f + __expf(-x)); }
__device__ __forceinline__ float tanhfast(float x) {
    return 2.0f / (1.0f + __expf(-2.0f * x)) - 1.0f;
}

__device__ __forceinline__ unsigned smem_u32(const void* p) {
    return (unsigned)__cvta_generic_to_shared(p);
}
__device__ __forceinline__ void cp16(unsigned dst, const void* src) {
    asm volatile("cp.async.cg.shared.global [%0], [%1], 16;" :: "r"(dst), "l"(src) : "memory");
}
__device__ __forceinline__ void cp_commit() {
    asm volatile("cp.async.commit_group;" ::: "memory");
}
__device__ __forceinline__ void cp_wait0() {
    asm volatile("cp.async.wait_group 0;" ::: "memory");
}

// mbarrier helpers ------------------------------------------------------------
__device__ __forceinline__ void mbar_init(unsigned addr, unsigned cnt) {
    asm volatile("mbarrier.init.shared.b64 [%0], %1;" :: "r"(addr), "r"(cnt) : "memory");
}
__device__ __forceinline__ void mbar_expect_tx(unsigned addr, unsigned bytes) {
    asm volatile("mbarrier.arrive.expect_tx.shared.b64 _, [%0], %1;"
                 :: "r"(addr), "r"(bytes) : "memory");
}
__device__ __forceinline__ void bulk_g2s(unsigned dst, const void* src,
                                         unsigned bytes, unsigned mbar) {
    asm volatile("cp.async.bulk.shared::cta.global.mbarrier::complete_tx::bytes "
                 "[%0], [%1], %2, [%3];"
                 :: "r"(dst), "l"(src), "r"(bytes), "r"(mbar) : "memory");
}
__device__ __forceinline__ void mbar_wait(unsigned addr, unsigned parity) {
    unsigned done;
    asm volatile(
        "{\n\t.reg .pred p;\n\t"
        "mbarrier.try_wait.parity.acquire.cta.shared::cta.b64 p, [%1], %2;\n\t"
        "selp.b32 %0, 1, 0, p;\n\t}"
        : "=r"(done) : "r"(addr), "r"(parity) : "memory");
    if (!done) {
        asm volatile(
            "{\n\t.reg .pred P1;\n\t"
            "WL_%=:\n\t"
            "mbarrier.try_wait.parity.acquire.cta.shared::cta.b64 P1, [%0], %1, 0x989680;\n\t"
            "@P1 bra.uni WD_%=;\n\t"
            "bra.uni WL_%=;\n\t"
            "WD_%=:\n\t}"
            :: "r"(addr), "r"(parity) : "memory");
    }
}

// ---------------------------------------------------------------------------
// Grid barrier: all NCTA CTAs resident. Tight spin (no nanosleep).
// ---------------------------------------------------------------------------
__device__ __forceinline__ void grid_barrier() {
    __syncthreads();
    if (threadIdx.x == 0) {
        unsigned gen = g_bar_gen;
        __threadfence();
        if (atomicAdd(&g_bar_count, 1u) == NCTA - 1) {
            g_bar_count = 0;
            __threadfence();
            g_bar_gen = gen + 1;
        } else {
            while (g_bar_gen == gen) { }
        }
        __threadfence();
    }
    __syncthreads();
}

// ---------------------------------------------------------------------------
// Phase 1 (unchanged, known-good)
// ---------------------------------------------------------------------------
__global__ void __launch_bounds__(256) phase1_kernel(
    const float* __restrict__ x,
    const float* __restrict__ Wf, const float* __restrict__ Wr,
    const float* __restrict__ bif, const float* __restrict__ bhf,
    const float* __restrict__ bir, const float* __restrict__ bhr)
{
    __shared__ __align__(16) float Wt[32][132];
    __shared__ __align__(16) float Xt[32][68];

    const int tid = threadIdx.x;
    const int n0  = blockIdx.x * 128;
    const int s   = blockIdx.y;
    const int dir = blockIdx.z;
    const int tt  = dir ? (TT - 1 - s) : s;
    const float* __restrict__ W = dir ? Wr : Wf;

    const int bg = tid & 15;
    const int ng = tid >> 4;

    u64 acc[8][2];
#pragma unroll
    for (int i = 0; i < 8; i++) { acc[i][0] = 0ull; acc[i][1] = 0ull; }

    const float* xbase = x + (size_t)tt * BB * DD;

    for (int d0 = 0; d0 < DD; d0 += 32) {
        __syncthreads();
#pragma unroll
        for (int i = 0; i < 4; i++) {
            int lin = tid + 256 * i;
            int n = lin >> 3, kq = lin & 7;
            float4 w = *(const float4*)(W + (size_t)(n0 + n) * DD + d0 + kq * 4);
            Wt[kq*4+0][n] = w.x; Wt[kq*4+1][n] = w.y;
            Wt[kq*4+2][n] = w.z; Wt[kq*4+3][n] = w.w;
        }
#pragma unroll
        for (int i = 0; i < 2; i++) {
            int lin = tid + 256 * i;
            int b = lin >> 3, kq = lin & 7;
            float4 v = *(const float4*)(xbase + (size_t)b * DD + d0 + kq * 4);
            Xt[kq*4+0][b] = v.x; Xt[kq*4+1][b] = v.y;
            Xt[kq*4+2][b] = v.z; Xt[kq*4+3][b] = v.w;
        }
        __syncthreads();
#pragma unroll 8
        for (int k = 0; k < 32; k++) {
            float4 xa = *(const float4*)&Xt[k][bg * 4];
            u64 xv0 = pk2(xa.x, xa.y);
            u64 xv1 = pk2(xa.z, xa.w);
            float wv[8];
            *(float4*)&wv[0] = *(const float4*)&Wt[k][ng * 8];
            *(float4*)&wv[4] = *(const float4*)&Wt[k][ng * 8 + 4];
#pragma unroll
            for (int i = 0; i < 8; i++) {
                u64 w = pk2(wv[i], wv[i]);
                fma2(acc[i][0], w, xv0);
                fma2(acc[i][1], w, xv1);
            }
        }
    }

    const float* bi = dir ? bir : bif;
    const float* bh = dir ? bhr : bhf;
    float* Gp = g_G + ((size_t)(dir * TT + s) * G4 + n0 + ng * 8) * BB;
#pragma unroll
    for (int i = 0; i < 8; i++) {
        int n = n0 + ng * 8 + i;
        float bsum = bi[n] + bh[n];
        float2 p0 = unpk(acc[i][0]);
        float2 p1 = unpk(acc[i][1]);
        float4 o = make_float4(p0.x + bsum, p0.y + bsum, p1.x + bsum, p1.y + bsum);
        *(float4*)(Gp + (size_t)i * BB + bg * 4) = o;
    }
}

// ---------------------------------------------------------------------------
// Phase 2 v4: R5 structure + overhead removal.
// SMEM floats: Ws[2][512][16]=16384 | hall[512][64]=32768 | Gs[32][64]=2048 |
//   gbuf2[2][32][64]=4096 | csm 512 | hosm 512 | Ms 64 | mbar pad 16
// ---------------------------------------------------------------------------
#define SM_WS    0
#define SM_HALL  16384
#define SM_GS    49152
#define SM_GBUF  51200
#define SM_CSM   55296
#define SM_HOSM  55808
#define SM_MS    56320
#define SM_MBAR  56384
#define SM_FLOATS 56400

__global__ void __launch_bounds__(256) phase2_kernel(
    const float* __restrict__ Whf, const float* __restrict__ Whr,
    const float* __restrict__ mask, float* __restrict__ out)
{
    extern __shared__ __align__(16) float sm[];
    float* Ws    = sm + SM_WS;
    float* hall  = sm + SM_HALL;
    float* Gs    = sm + SM_GS;
    float* gbuf2 = sm + SM_GBUF;
    float* csm   = sm + SM_CSM;
    float* hosm  = sm + SM_HOSM;
    float* Ms    = sm + SM_MS;
    const unsigned mbar0   = smem_u32(sm + SM_MBAR);
    const unsigned gs_sa   = smem_u32(Gs);
    const unsigned ms_sa   = smem_u32(Ms);
    const unsigned hall_sa = smem_u32(hall);

    const int tid = threadIdx.x;
    const int cid = blockIdx.x;
    const int dir = cid >> 6;
    const int j0  = (cid & 63) * 8;
    const float* __restrict__ Whh = dir ? Whr : Whf;

    // init: Ws[rg][k][16] = Whh rows 16rg+rloc at col k
    for (int i = tid; i < 32 * 512; i += 256) {
        int rr = i >> 9, k = i & 511;
        int rg = rr >> 4, rloc = rr & 15;
        int gate = rr >> 3, u = rr & 7;
        Ws[((size_t)rg * 512 + k) * 16 + rloc] =
            Whh[(size_t)(gate * HH + j0 + u) * HH + k];
    }
    for (int i = tid; i < 8 * 64; i += 256) {
        csm[i] = 0.0f;
        hosm[i] = 0.0f;
        g_h[0][dir][j0 + (i >> 6)][i & 63] = 0.0f;
    }
    if (tid < 4) mbar_init(mbar0 + tid * 8, 1);
    __syncthreads();
    asm volatile("fence.proxy.async.shared::cta;" ::: "memory");

    // G + mask prefetch for step 0
    {
        const float* base = g_G + (size_t)(dir * TT) * G4 * BB;
#pragma unroll
        for (int i = 0; i < 2; i++) {
            int q = tid + 256 * i;
            int gate = q >> 7, off = q & 127;
            const float* src = base + ((size_t)(gate * HH + j0)) * BB + off * 4;
            cp16(gs_sa + (unsigned)(gate * 512 + off * 4) * 4, src);
        }
        if (tid < 16) {
            int tg0 = dir ? (TT - 1) : 0;
            cp16(ms_sa + (unsigned)tid * 16, mask + (size_t)tg0 * BB + tid * 4);
        }
        cp_commit();
    }
    grid_barrier();
    cp_wait0();
    __syncthreads();

    const int w    = tid >> 5;
    const int lane = tid & 31;
    const int rg   = w & 1;
    const int bh   = (w >> 1) & 1;
    const int kh   = w >> 2;
    const int b    = bh * 32 + lane;
    const float* wbase = Ws + ((size_t)rg * 512 + kh * 256) * 16;
    const float* hbase = hall + (kh * 256) * 64 + b;

    for (int s = 0; s < TT; s++) {
        const int pb = s & 1, nb = pb ^ 1;
        const int tg = dir ? (TT - 1 - s) : s;

        // issue 4 bulk copies of h[pb] from lane 0 of warps 0..3
        if (lane == 0 && w < 4) {
            unsigned mb = mbar0 + w * 8;
            mbar_expect_tx(mb, 32768u);
            bulk_g2s(hall_sa + (unsigned)w * 32768u,
                     &g_h[pb][dir][w * 128][0], 32768u, mb);
        }

        // accumulators: kh=0 carries G (input preact + bias), kh=1 zero
        u64 acc[8];
        if (kh == 0) {
            const float* Gp = Gs + (rg * 16) * 64 + b;
#pragma unroll
            for (int rp = 0; rp < 8; rp++)
                acc[rp] = pk2(Gp[(2 * rp) * 64], Gp[(2 * rp + 1) * 64]);
        } else {
#pragma unroll
            for (int rp = 0; rp < 8; rp++) acc[rp] = 0ull;
        }

        // k-loop over this warp's two 128-k chunks
#pragma unroll
        for (int half = 0; half < 2; half++) {
            mbar_wait(mbar0 + (kh * 2 + half) * 8, (unsigned)(s & 1));
            const float* wp = wbase + (size_t)half * 128 * 16;
            const float* hp = hbase + (size_t)half * 128 * 64;
#pragma unroll 8
            for (int k = 0; k < 128; k++) {
                float hv = hp[(size_t)k * 64];
                u64 hd = pk2(hv, hv);
                const float* wk = wp + (size_t)k * 16;
                ulonglong2 w01 = *(const ulonglong2*)(wk);
                ulonglong2 w23 = *(const ulonglong2*)(wk + 4);
                ulonglong2 w45 = *(const ulonglong2*)(wk + 8);
                ulonglong2 w67 = *(const ulonglong2*)(wk + 12);
                fma2(acc[0], w01.x, hd); fma2(acc[1], w01.y, hd);
                fma2(acc[2], w23.x, hd); fma2(acc[3], w23.y, hd);
                fma2(acc[4], w45.x, hd); fma2(acc[5], w45.y, hd);
                fma2(acc[6], w67.x, hd); fma2(acc[7], w67.y, hd);
            }
        }

        // write partials
        {
            float* gb = gbuf2 + kh * 2048 + (rg * 16) * 64 + b;
#pragma unroll
            for (int rp = 0; rp < 8; rp++) {
                float2 v = unpk(acc[rp]);
                gb[(2 * rp) * 64]     = v.x;
                gb[(2 * rp + 1) * 64] = v.y;
            }
        }
        __syncthreads();

        // gates, state update, mask blend, h publish
        {
            const int eb = tid & 63;
            const float m = Ms[eb];
#pragma unroll
            for (int it = 0; it < 2; it++) {
                const int u = (tid >> 6) + it * 4;
                float pi = gbuf2[(u)      * 64 + eb] + gbuf2[2048 + (u)      * 64 + eb];
                float pf = gbuf2[(8 + u)  * 64 + eb] + gbuf2[2048 + (8 + u)  * 64 + eb];
                float pg = gbuf2[(16 + u) * 64 + eb] + gbuf2[2048 + (16 + u) * 64 + eb];
                float po = gbuf2[(24 + u) * 64 + eb] + gbuf2[2048 + (24 + u) * 64 + eb];
                float ig = sigf(pi);
                float fg = sigf(pf);
                float gg = tanhfast(pg);
                float og = sigf(po);
                float c_old = csm[u * 64 + eb];
                float c2 = fg * c_old + ig * gg;
                float h2 = og * tanhfast(c2);
                float c_new = c_old + m * (c2 - c_old);
                float h_old = hosm[eb * 8 + u];
                float h_new = h_old + m * (h2 - h_old);
                csm[u * 64 + eb] = c_new;
                hosm[eb * 8 + u] = h_new;
                g_h[nb][dir][j0 + u][eb] = h_new;
            }
        }
        __syncthreads();

        // coalesced output store
        if (tid < 128) {
            const int ob = tid >> 1, half = tid & 1;
            *(float4*)&out[(size_t)tg * (BB * 1024) + (size_t)ob * 1024
                           + dir * HH + j0 + half * 4]
                = *(const float4*)&hosm[ob * 8 + half * 4];
        }

        if (s + 1 < TT) {
            // G + mask prefetch for s+1 (hides under barrier)
            const float* base = g_G + (size_t)(dir * TT + (s + 1)) * G4 * BB;
#pragma unroll
            for (int i = 0; i < 2; i++) {
                int q = tid + 256 * i;
                int gate = q >> 7, off = q & 127;
                const float* src = base + ((size_t)(gate * HH + j0)) * BB + off * 4;
                cp16(gs_sa + (unsigned)(gate * 512 + off * 4) * 4, src);
            }
            if (tid < 16) {
                int tg2 = dir ? (TT - 2 - s) : (s + 1);
                cp16(ms_sa + (unsigned)tid * 16, mask + (size_t)tg2 * BB + tid * 4);
            }
            cp_commit();
            grid_barrier();
            cp_wait0();
            __syncthreads();
        }
    }
}

// ---------------------------------------------------------------------------
// Launch
// ---------------------------------------------------------------------------
extern "C" void kernel_launch(void* const* d_in, const int* in_sizes, int n_in,
                              void* d_out, int out_size) {
    const float* x_data = (const float*)d_in[0];
    const float* x_mask = (const float*)d_in[1];
    const float* Wih_f  = (const float*)d_in[2];
    const float* Whh_f  = (const float*)d_in[3];
    const float* bih_f  = (const float*)d_in[4];
    const float* bhh_f  = (const float*)d_in[5];
    const float* Wih_r  = (const float*)d_in[6];
    const float* Whh_r  = (const float*)d_in[7];
    const float* bih_r  = (const float*)d_in[8];
    const float* bhh_r  = (const float*)d_in[9];
    float* out = (float*)d_out;

    static bool attr_set = false;
    if (!attr_set) {
        cudaFuncSetAttribute(phase2_kernel,
                             cudaFuncAttributeMaxDynamicSharedMemorySize,
                             SM_FLOATS * 4);
        attr_set = true;
    }

    dim3 g1(16, 512, 2);
    phase1_kernel<<<g1, 256>>>(x_data, Wih_f, Wih_r, bih_f, bhh_f, bih_r, bhh_r);
    phase2_kernel<<<NCTA, 256, SM_FLOATS * 4>>>(Whh_f, Whh_r, x_mask, out);
}

// round 7
// speedup vs baseline: 2.2801x; 1.0313x over previous
#include <cuda_runtime.h>
#include <cstdint>

typedef unsigned long long u64;

#define TT 512
#define BB 64
#define DD 512
#define HH 512
#define G4 2048
#define NCTA 128

// ---------------------------------------------------------------------------
// Device-global scratch
// ---------------------------------------------------------------------------
__device__ float g_G[(size_t)2 * TT * G4 * BB];   // 512 MB precomputed x@Wih^T + bias
__device__ float g_h[2][2][HH][BB];               // [buf][dir][k][b]
__device__ unsigned g_bar_count;
__device__ volatile unsigned g_bar_gen;

// ---------------------------------------------------------------------------
// f32x2 packed helpers (sm_103a FFMA2)
// ---------------------------------------------------------------------------
__device__ __forceinline__ u64 pk2(float a, float b) {
    u64 r; asm("mov.b64 %0, {%1,%2};" : "=l"(r) : "f"(a), "f"(b)); return r;
}
__device__ __forceinline__ void fma2(u64& d, u64 a, u64 b) {
    asm("fma.rn.f32x2 %0, %1, %2, %0;" : "+l"(d) : "l"(a), "l"(b));
}
__device__ __forceinline__ float2 unpk(u64 v) {
    float2 r; asm("mov.b64 {%0,%1}, %2;" : "=f"(r.x), "=f"(r.y) : "l"(v)); return r;
}
__device__ __forceinline__ float sigf(float x)  { return 1.0f / (1.0f + __expf(-x)); }
__device__ __forceinline__ float tanhfast(float x) {
    return 2.0f / (1.0f + __expf(-2.0f * x)) - 1.0f;
}

__device__ __forceinline__ unsigned smem_u32(const void* p) {
    return (unsigned)__cvta_generic_to_shared(p);
}
__device__ __forceinline__ void cp16(unsigned dst, const void* src) {
    asm volatile("cp.async.cg.shared.global [%0], [%1], 16;" :: "r"(dst), "l"(src) : "memory");
}
__device__ __forceinline__ void cp_commit() {
    asm volatile("cp.async.commit_group;" ::: "memory");
}
__device__ __forceinline__ void cp_wait0() {
    asm volatile("cp.async.wait_group 0;" ::: "memory");
}

// mbarrier helpers ------------------------------------------------------------
__device__ __forceinline__ void mbar_init(unsigned addr, unsigned cnt) {
    asm volatile("mbarrier.init.shared.b64 [%0], %1;" :: "r"(addr), "r"(cnt) : "memory");
}
__device__ __forceinline__ void mbar_expect_tx(unsigned addr, unsigned bytes) {
    asm volatile("mbarrier.arrive.expect_tx.shared.b64 _, [%0], %1;"
                 :: "r"(addr), "r"(bytes) : "memory");
}
__device__ __forceinline__ void bulk_g2s(unsigned dst, const void* src,
                                         unsigned bytes, unsigned mbar) {
    asm volatile("cp.async.bulk.shared::cta.global.mbarrier::complete_tx::bytes "
                 "[%0], [%1], %2, [%3];"
                 :: "r"(dst), "l"(src), "r"(bytes), "r"(mbar) : "memory");
}
__device__ __forceinline__ void mbar_wait(unsigned addr, unsigned parity) {
    unsigned done;
    asm volatile(
        "{\n\t.reg .pred p;\n\t"
        "mbarrier.try_wait.parity.acquire.cta.shared::cta.b64 p, [%1], %2;\n\t"
        "selp.b32 %0, 1, 0, p;\n\t}"
        : "=r"(done) : "r"(addr), "r"(parity) : "memory");
    if (!done) {
        asm volatile(
            "{\n\t.reg .pred P1;\n\t"
            "WL_%=:\n\t"
            "mbarrier.try_wait.parity.acquire.cta.shared::cta.b64 P1, [%0], %1, 0x989680;\n\t"
            "@P1 bra.uni WD_%=;\n\t"
            "bra.uni WL_%=;\n\t"
            "WD_%=:\n\t}"
            :: "r"(addr), "r"(parity) : "memory");
    }
}

// ---------------------------------------------------------------------------
// Grid barrier: all NCTA CTAs resident. Tight spin.
// ---------------------------------------------------------------------------
__device__ __forceinline__ void grid_barrier() {
    __syncthreads();
    if (threadIdx.x == 0) {
        unsigned gen = g_bar_gen;
        __threadfence();
        if (atomicAdd(&g_bar_count, 1u) == NCTA - 1) {
            g_bar_count = 0;
            __threadfence();
            g_bar_gen = gen + 1;
        } else {
            while (g_bar_gen == gen) { }
        }
        __threadfence();
    }
    __syncthreads();
}

// ---------------------------------------------------------------------------
// Phase 1 (unchanged, known-good)
// ---------------------------------------------------------------------------
__global__ void __launch_bounds__(256) phase1_kernel(
    const float* __restrict__ x,
    const float* __restrict__ Wf, const float* __restrict__ Wr,
    const float* __restrict__ bif, const float* __restrict__ bhf,
    const float* __restrict__ bir, const float* __restrict__ bhr)
{
    __shared__ __align__(16) float Wt[32][132];
    __shared__ __align__(16) float Xt[32][68];

    const int tid = threadIdx.x;
    const int n0  = blockIdx.x * 128;
    const int s   = blockIdx.y;
    const int dir = blockIdx.z;
    const int tt  = dir ? (TT - 1 - s) : s;
    const float* __restrict__ W = dir ? Wr : Wf;

    const int bg = tid & 15;
    const int ng = tid >> 4;

    u64 acc[8][2];
#pragma unroll
    for (int i = 0; i < 8; i++) { acc[i][0] = 0ull; acc[i][1] = 0ull; }

    const float* xbase = x + (size_t)tt * BB * DD;

    for (int d0 = 0; d0 < DD; d0 += 32) {
        __syncthreads();
#pragma unroll
        for (int i = 0; i < 4; i++) {
            int lin = tid + 256 * i;
            int n = lin >> 3, kq = lin & 7;
            float4 w = *(const float4*)(W + (size_t)(n0 + n) * DD + d0 + kq * 4);
            Wt[kq*4+0][n] = w.x; Wt[kq*4+1][n] = w.y;
            Wt[kq*4+2][n] = w.z; Wt[kq*4+3][n] = w.w;
        }
#pragma unroll
        for (int i = 0; i < 2; i++) {
            int lin = tid + 256 * i;
            int b = lin >> 3, kq = lin & 7;
            float4 v = *(const float4*)(xbase + (size_t)b * DD + d0 + kq * 4);
            Xt[kq*4+0][b] = v.x; Xt[kq*4+1][b] = v.y;
            Xt[kq*4+2][b] = v.z; Xt[kq*4+3][b] = v.w;
        }
        __syncthreads();
#pragma unroll 8
        for (int k = 0; k < 32; k++) {
            float4 xa = *(const float4*)&Xt[k][bg * 4];
            u64 xv0 = pk2(xa.x, xa.y);
            u64 xv1 = pk2(xa.z, xa.w);
            float wv[8];
            *(float4*)&wv[0] = *(const float4*)&Wt[k][ng * 8];
            *(float4*)&wv[4] = *(const float4*)&Wt[k][ng * 8 + 4];
#pragma unroll
            for (int i = 0; i < 8; i++) {
                u64 w = pk2(wv[i], wv[i]);
                fma2(acc[i][0], w, xv0);
                fma2(acc[i][1], w, xv1);
            }
        }
    }

    const float* bi = dir ? bir : bif;
    const float* bh = dir ? bhr : bhf;
    float* Gp = g_G + ((size_t)(dir * TT + s) * G4 + n0 + ng * 8) * BB;
#pragma unroll
    for (int i = 0; i < 8; i++) {
        int n = n0 + ng * 8 + i;
        float bsum = bi[n] + bh[n];
        float2 p0 = unpk(acc[i][0]);
        float2 p1 = unpk(acc[i][1]);
        float4 o = make_float4(p0.x + bsum, p0.y + bsum, p1.x + bsum, p1.y + bsum);
        *(float4*)(Gp + (size_t)i * BB + bg * 4) = o;
    }
}

// ---------------------------------------------------------------------------
// Phase 2 v5: 512 threads / 16 warps, k split in quarters.
// Warp (kh,rg,bh): rows 16rg..+15, b = 32bh+lane, k in [128kh, 128kh+128).
// Partials: kh 0/1 write planes 0/1; kh 2/3 add into planes 0/1 (2-pass).
// Each warp waits only its own h bulk-copy chunk (kh).
// SMEM floats (unchanged layout): Ws 16384 | hall 32768 | Gs 2048 |
//   gbuf2 4096 | csm 512 | hosm 512 | Ms 64 | mbar pad 16
// ---------------------------------------------------------------------------
#define SM_WS    0
#define SM_HALL  16384
#define SM_GS    49152
#define SM_GBUF  51200
#define SM_CSM   55296
#define SM_HOSM  55808
#define SM_MS    56320
#define SM_MBAR  56384
#define SM_FLOATS 56400

__global__ void __launch_bounds__(512) phase2_kernel(
    const float* __restrict__ Whf, const float* __restrict__ Whr,
    const float* __restrict__ mask, float* __restrict__ out)
{
    extern __shared__ __align__(16) float sm[];
    float* Ws    = sm + SM_WS;
    float* hall  = sm + SM_HALL;
    float* Gs    = sm + SM_GS;
    float* gbuf2 = sm + SM_GBUF;
    float* csm   = sm + SM_CSM;
    float* hosm  = sm + SM_HOSM;
    float* Ms    = sm + SM_MS;
    const unsigned mbar0   = smem_u32(sm + SM_MBAR);
    const unsigned gs_sa   = smem_u32(Gs);
    const unsigned ms_sa   = smem_u32(Ms);
    const unsigned hall_sa = smem_u32(hall);

    const int tid = threadIdx.x;
    const int cid = blockIdx.x;
    const int dir = cid >> 6;
    const int j0  = (cid & 63) * 8;
    const float* __restrict__ Whh = dir ? Whr : Whf;

    // init: Ws[rg][k][16] = Whh rows 16rg+rloc at col k
    for (int i = tid; i < 32 * 512; i += 512) {
        int rr = i >> 9, k = i & 511;
        int rg2 = rr >> 4, rloc = rr & 15;
        int gate = rr >> 3, u = rr & 7;
        Ws[((size_t)rg2 * 512 + k) * 16 + rloc] =
            Whh[(size_t)(gate * HH + j0 + u) * HH + k];
    }
    if (tid < 512) {
        int i = tid;
        if (i < 8 * 64) { /* covered below */ }
    }
    for (int i = tid; i < 8 * 64; i += 512) {
        csm[i] = 0.0f;
        hosm[i] = 0.0f;
        g_h[0][dir][j0 + (i >> 6)][i & 63] = 0.0f;
    }
    if (tid < 4) mbar_init(mbar0 + tid * 8, 1);
    __syncthreads();
    asm volatile("fence.proxy.async.shared::cta;" ::: "memory");

    // G + mask prefetch for step 0
    {
        const float* base = g_G + (size_t)(dir * TT) * G4 * BB;
        int q = tid;                         // 0..511, one cp16 each
        int gate = q >> 7, off = q & 127;
        const float* src = base + ((size_t)(gate * HH + j0)) * BB + off * 4;
        cp16(gs_sa + (unsigned)(gate * 512 + off * 4) * 4, src);
        if (tid < 16) {
            int tg0 = dir ? (TT - 1) : 0;
            cp16(ms_sa + (unsigned)tid * 16, mask + (size_t)tg0 * BB + tid * 4);
        }
        cp_commit();
    }
    grid_barrier();
    cp_wait0();
    __syncthreads();

    const int w    = tid >> 5;
    const int lane = tid & 31;
    const int kh   = w >> 2;                 // 0..3 (k quarter)
    const int rg   = (w >> 1) & 1;           // row group
    const int bh   = w & 1;                  // batch half
    const int b    = bh * 32 + lane;
    const float* wbase = Ws + ((size_t)rg * 512 + kh * 128) * 16;
    const float* hbase = hall + (kh * 128) * 64 + b;
    float* gb = gbuf2 + (kh & 1) * 2048 + (rg * 16) * 64 + b;

    for (int s = 0; s < TT; s++) {
        const int pb = s & 1, nb = pb ^ 1;
        const int tg = dir ? (TT - 1 - s) : s;

        // issue 4 bulk copies of h[pb] (chunk w) from lane 0 of warps 0..3
        if (lane == 0 && w < 4) {
            unsigned mb = mbar0 + w * 8;
            mbar_expect_tx(mb, 32768u);
            bulk_g2s(hall_sa + (unsigned)w * 32768u,
                     &g_h[pb][dir][w * 128][0], 32768u, mb);
        }

        // accumulators: kh=0 carries G (input preact + bias)
        u64 acc[8];
        if (kh == 0) {
            const float* Gp = Gs + (rg * 16) * 64 + b;
#pragma unroll
            for (int rp = 0; rp < 8; rp++)
                acc[rp] = pk2(Gp[(2 * rp) * 64], Gp[(2 * rp + 1) * 64]);
        } else {
#pragma unroll
            for (int rp = 0; rp < 8; rp++) acc[rp] = 0ull;
        }

        // GEMM over this warp's 128-k quarter
        mbar_wait(mbar0 + kh * 8, (unsigned)(s & 1));
#pragma unroll 8
        for (int k = 0; k < 128; k++) {
            float hv = hbase[(size_t)k * 64];
            u64 hd = pk2(hv, hv);
            const float* wk = wbase + (size_t)k * 16;
            ulonglong2 w01 = *(const ulonglong2*)(wk);
            ulonglong2 w23 = *(const ulonglong2*)(wk + 4);
            ulonglong2 w45 = *(const ulonglong2*)(wk + 8);
            ulonglong2 w67 = *(const ulonglong2*)(wk + 12);
            fma2(acc[0], w01.x, hd); fma2(acc[1], w01.y, hd);
            fma2(acc[2], w23.x, hd); fma2(acc[3], w23.y, hd);
            fma2(acc[4], w45.x, hd); fma2(acc[5], w45.y, hd);
            fma2(acc[6], w67.x, hd); fma2(acc[7], w67.y, hd);
        }

        // 2-pass partial reduction into 2 planes
        if (kh < 2) {
#pragma unroll
            for (int rp = 0; rp < 8; rp++) {
                float2 v = unpk(acc[rp]);
                gb[(2 * rp) * 64]     = v.x;
                gb[(2 * rp + 1) * 64] = v.y;
            }
        }
        __syncthreads();
        if (kh >= 2) {
#pragma unroll
            for (int rp = 0; rp < 8; rp++) {
                float2 v = unpk(acc[rp]);
                gb[(2 * rp) * 64]     += v.x;
                gb[(2 * rp + 1) * 64] += v.y;
            }
        }
        __syncthreads();

        // gates, state update, mask blend, h publish (512 threads, 1 pass)
        {
            const int eb = tid & 63;
            const int u  = tid >> 6;         // 0..7
            const float m = Ms[eb];
            float pi = gbuf2[(u)      * 64 + eb] + gbuf2[2048 + (u)      * 64 + eb];
            float pf = gbuf2[(8 + u)  * 64 + eb] + gbuf2[2048 + (8 + u)  * 64 + eb];
            float pg = gbuf2[(16 + u) * 64 + eb] + gbuf2[2048 + (16 + u) * 64 + eb];
            float po = gbuf2[(24 + u) * 64 + eb] + gbuf2[2048 + (24 + u) * 64 + eb];
            float ig = sigf(pi);
            float fg = sigf(pf);
            float gg = tanhfast(pg);
            float og = sigf(po);
            float c_old = csm[u * 64 + eb];
            float c2 = fg * c_old + ig * gg;
            float h2 = og * tanhfast(c2);
            float c_new = c_old + m * (c2 - c_old);
            float h_old = hosm[eb * 8 + u];
            float h_new = h_old + m * (h2 - h_old);
            csm[u * 64 + eb] = c_new;
            hosm[eb * 8 + u] = h_new;
            g_h[nb][dir][j0 + u][eb] = h_new;
        }
        __syncthreads();

        // coalesced output store
        if (tid < 128) {
            const int ob = tid >> 1, half = tid & 1;
            *(float4*)&out[(size_t)tg * (BB * 1024) + (size_t)ob * 1024
                           + dir * HH + j0 + half * 4]
                = *(const float4*)&hosm[ob * 8 + half * 4];
        }

        if (s + 1 < TT) {
            // G + mask prefetch for s+1 (hides under barrier)
            const float* base = g_G + (size_t)(dir * TT + (s + 1)) * G4 * BB;
            int q = tid;
            int gate = q >> 7, off = q & 127;
            const float* src = base + ((size_t)(gate * HH + j0)) * BB + off * 4;
            cp16(gs_sa + (unsigned)(gate * 512 + off * 4) * 4, src);
            if (tid < 16) {
                int tg2 = dir ? (TT - 2 - s) : (s + 1);
                cp16(ms_sa + (unsigned)tid * 16, mask + (size_t)tg2 * BB + tid * 4);
            }
            cp_commit();
            grid_barrier();
            cp_wait0();
            __syncthreads();
        }
    }
}

// ---------------------------------------------------------------------------
// Launch
// ---------------------------------------------------------------------------
extern "C" void kernel_launch(void* const* d_in, const int* in_sizes, int n_in,
                              void* d_out, int out_size) {
    const float* x_data = (const float*)d_in[0];
    const float* x_mask = (const float*)d_in[1];
    const float* Wih_f  = (const float*)d_in[2];
    const float* Whh_f  = (const float*)d_in[3];
    const float* bih_f  = (const float*)d_in[4];
    const float* bhh_f  = (const float*)d_in[5];
    const float* Wih_r  = (const float*)d_in[6];
    const float* Whh_r  = (const float*)d_in[7];
    const float* bih_r  = (const float*)d_in[8];
    const float* bhh_r  = (const float*)d_in[9];
    float* out = (float*)d_out;

    static bool attr_set = false;
    if (!attr_set) {
        cudaFuncSetAttribute(phase2_kernel,
                             cudaFuncAttributeMaxDynamicSharedMemorySize,
                             SM_FLOATS * 4);
        attr_set = true;
    }

    dim3 g1(16, 512, 2);
    phase1_kernel<<<g1, 256>>>(x_data, Wih_f, Wih_r, bih_f, bhh_f, bih_r, bhh_r);
    phase2_kernel<<<NCTA, 512, SM_FLOATS * 4>>>(Whh_f, Whh_r, x_mask, out);
}